// round 9
// baseline (speedup 1.0000x reference)
#include <cuda_runtime.h>
#include <cuda_fp16.h>
#include <cstdint>

#define NBLOCKS 6250
#define ACHUNK_BYTES (128 * 128)            // 128 rows x 64 fp16 cols
#define SMEM_BYTES (2 * ACHUNK_BYTES + 512)

// fp16 B fragments for mma.m16n8k16, with OUTPUT-COLUMN PERMUTATION so that
// thread t's C pairs across nt are 16 consecutive columns:
//   slot (wn, ks, lane(g,t), nt, j) holds W row
//   n = wn*64 + (g>>1)*16 + nt*2 + (g&1),  k = ks*16 + 2t + 8j
__device__ uint32_t g_Bf16[16384];          // 64 KB, L1/L2-resident

__global__ void prep_b16(const float* __restrict__ W) {
    int i = blockIdx.x * 256 + threadIdx.x;   // 0..16383
    int wn   = i >> 13;
    int rem  = i & 8191;
    int ks   = rem >> 9;
    int rem2 = rem & 511;
    int lane = rem2 >> 4;
    int idx  = rem2 & 15;
    int nt = idx >> 1, j = idx & 1;
    int g = lane >> 2, t = lane & 3;
    int n = wn * 64 + ((g >> 1) << 4) + nt * 2 + (g & 1);   // permuted col map
    int k = ks * 16 + 2 * t + 8 * j;
    __half2 h = __floats2half2_rn(W[n * 256 + k], W[n * 256 + k + 1]);
    g_Bf16[i] = *(uint32_t*)&h;
}

__device__ __forceinline__ uint32_t smem_u32(const void* p) {
    uint32_t a;
    asm("{ .reg .u64 t; cvta.to.shared.u64 t, %1; cvt.u32.u64 %0, t; }" : "=r"(a) : "l"(p));
    return a;
}
__device__ __forceinline__ uint32_t swz(uint32_t b) {   // 128B rows, 8-row period
    return b ^ (((b >> 7) & 7) << 4);
}
__device__ __forceinline__ uint32_t pack_h2(float x, float y) {
    __half2 h = __floats2half2_rn(x, y);
    return *(uint32_t*)&h;
}
__device__ __forceinline__ void ldsm4(uint32_t& a0, uint32_t& a1, uint32_t& a2,
                                      uint32_t& a3, uint32_t addr) {
    asm volatile("ldmatrix.sync.aligned.m8n8.x4.shared.b16 {%0,%1,%2,%3}, [%4];"
                 : "=r"(a0), "=r"(a1), "=r"(a2), "=r"(a3) : "r"(addr));
}
__device__ __forceinline__ void mma16(float* acc, uint32_t a0, uint32_t a1,
                                      uint32_t a2, uint32_t a3,
                                      uint32_t b0, uint32_t b1) {
    asm volatile(
        "mma.sync.aligned.m16n8k16.row.col.f32.f16.f16.f32 "
        "{%0,%1,%2,%3}, {%4,%5,%6,%7}, {%8,%9}, {%0,%1,%2,%3};\n"
        : "+f"(acc[0]), "+f"(acc[1]), "+f"(acc[2]), "+f"(acc[3])
        : "r"(a0), "r"(a1), "r"(a2), "r"(a3), "r"(b0), "r"(b1));
}

// CTA: 128 edges x 128 outputs. 128 threads = 4 warps (2M x 2N), 64x64 warp tile.
// A fp16-converted at load (LDG->F2FP->STS), fragments via ldmatrix.x4 from
// swizzled smem. B fp16 fragments via LDG (L1-hot). Epilogue STG.128-contiguous.
__global__ void __launch_bounds__(128, 2) msg_mma_kernel(
    const float* __restrict__ H,
    const float* __restrict__ E,
    const int*   __restrict__ heads,
    const float* __restrict__ bias,
    float*       __restrict__ out)
{
    extern __shared__ __align__(1024) char smem[];
    float* bias_s = (float*)(smem + 2 * ACHUNK_BYTES);
    const uint32_t sbase = smem_u32(smem);

    const int tid  = threadIdx.x;
    const int warp = tid >> 5;
    const int lane = tid & 31;
    const int warp_m = warp >> 1;
    const int warp_n = warp & 1;
    const int g = lane >> 2;
    const int t = lane & 3;
    const int block_m = blockIdx.x * 128;

    bias_s[tid] = bias[tid];

    // ---- A staging: thread covers rows (tid>>2)+32i, float cols (tid&3)*16.. ----
    const int arow = tid >> 2;
    const int aseg = (tid & 3) * 16;
    const float* hsrc[4];
    const float* esrc[4];
    uint32_t sts_a[4], sts_b[4];
    #pragma unroll
    for (int i = 0; i < 4; i++) {
        const int r = arow + 32 * i;
        hsrc[i] = H + (size_t)heads[block_m + r] * 128 + aseg;
        esrc[i] = E + (size_t)(block_m + r) * 128 + aseg;
        const uint32_t byt = (uint32_t)(r * 128 + aseg * 2);
        sts_a[i] = swz(byt);
        sts_b[i] = swz(byt + 16);
    }

    uint4 stg0[4][2], stg1[4][2];
    auto ldg_chunk = [&](int c, uint4 stg[4][2]) {
        #pragma unroll
        for (int i = 0; i < 4; i++) {
            const float* s = ((c < 2) ? hsrc[i] : esrc[i]) + (c & 1) * 64;
            float4 v0 = *(const float4*)(s + 0);
            float4 v1 = *(const float4*)(s + 4);
            float4 v2 = *(const float4*)(s + 8);
            float4 v3 = *(const float4*)(s + 12);
            stg[i][0] = make_uint4(pack_h2(v0.x, v0.y), pack_h2(v0.z, v0.w),
                                   pack_h2(v1.x, v1.y), pack_h2(v1.z, v1.w));
            stg[i][1] = make_uint4(pack_h2(v2.x, v2.y), pack_h2(v2.z, v2.w),
                                   pack_h2(v3.x, v3.y), pack_h2(v3.z, v3.w));
        }
    };
    auto sts_chunk = [&](int buf, uint4 stg[4][2]) {
        const uint32_t off = (uint32_t)(buf * ACHUNK_BYTES);
        #pragma unroll
        for (int i = 0; i < 4; i++) {
            *(uint4*)(smem + off + sts_a[i]) = stg[i][0];
            *(uint4*)(smem + off + sts_b[i]) = stg[i][1];
        }
    };

    // ---- ldmatrix lane bases per mt: UNSWIZZLED; XOR mask applied at use ----
    const int row_sel = (lane & 7) + ((lane >> 3) & 1) * 8;
    const int kb2     = ((lane >> 4) & 1) * 16;
    const uint32_t xmask = (uint32_t)((lane & 7) << 4);
    uint32_t lm[4];
    #pragma unroll
    for (int mt = 0; mt < 4; mt++) {
        const int row0 = warp_m * 64 + mt * 16;
        lm[mt] = sbase + (uint32_t)((row0 + row_sel) * 128 + kb2);
    }

    float acc[2][8][4];
    float acc2[2][8][4];
    #pragma unroll
    for (int mt = 0; mt < 2; mt++)
        #pragma unroll
        for (int nt = 0; nt < 8; nt++)
            #pragma unroll
            for (int i = 0; i < 4; i++) { acc[mt][nt][i] = 0.0f; acc2[mt][nt][i] = 0.0f; }

    auto compute = [&](int c) {
        const uint32_t bufoff = (uint32_t)((c & 1) * ACHUNK_BYTES);
        #pragma unroll
        for (int ksl = 0; ksl < 4; ksl++) {
            const int ks = c * 4 + ksl;
            const uint4* bp = (const uint4*)g_Bf16 + ((warp_n * 16 + ks) * 32 + lane) * 4;
            uint4 q0 = bp[0], q1 = bp[1], q2 = bp[2], q3 = bp[3];
            uint32_t bf[8][2] = {
                {q0.x, q0.y}, {q0.z, q0.w},
                {q1.x, q1.y}, {q1.z, q1.w},
                {q2.x, q2.y}, {q2.z, q2.w},
                {q3.x, q3.y}, {q3.z, q3.w}};
            #pragma unroll
            for (int mt = 0; mt < 4; mt++) {
                uint32_t a0, a1, a2, a3;
                ldsm4(a0, a1, a2, a3,
                      (lm[mt] + bufoff + (uint32_t)(ksl * 32)) ^ xmask);
                float* arow_p = (mt < 2) ? acc[mt][0] : acc2[mt - 2][0];
                #pragma unroll
                for (int nt = 0; nt < 8; nt++)
                    mma16(arow_p + nt * 4, a0, a1, a2, a3, bf[nt][0], bf[nt][1]);
            }
        }
    };

    // ---- pipeline: LDG of chunk c+2 hidden under compute of chunk c ----
    ldg_chunk(0, stg0); sts_chunk(0, stg0);
    ldg_chunk(1, stg1); sts_chunk(1, stg1);
    ldg_chunk(2, stg0);
    __syncthreads();
    compute(0);
    __syncthreads();
    sts_chunk(0, stg0);
    ldg_chunk(3, stg1);
    __syncthreads();
    compute(1);
    __syncthreads();
    sts_chunk(1, stg1);
    __syncthreads();
    compute(2);
    compute(3);

    // ---- Epilogue: permuted layout -> thread t owns cols [warp_n*64+16t, +16)
    //      of rows g / g+8 per mt. Fully contiguous STG.128. ----
    const int col0 = warp_n * 64 + t * 16;
    #pragma unroll
    for (int mt = 0; mt < 4; mt++) {
        const float* arow_p = (mt < 2) ? acc[mt][0] : acc2[mt - 2][0];
        const size_t rlo = (size_t)(block_m + warp_m * 64 + mt * 16 + g) * 128;
        #pragma unroll
        for (int np = 0; np < 4; np++) {
            float4 bv = *(const float4*)(bias_s + col0 + 4 * np);
            const float* aA = arow_p + (2 * np) * 4;       // acc[mt][2np]
            const float* aB = arow_p + (2 * np + 1) * 4;   // acc[mt][2np+1]
            float4 v0, v1;
            v0.x = aA[0] + bv.x; v0.y = aA[1] + bv.y;
            v0.z = aB[0] + bv.z; v0.w = aB[1] + bv.w;
            v1.x = aA[2] + bv.x; v1.y = aA[3] + bv.y;
            v1.z = aB[2] + bv.z; v1.w = aB[3] + bv.w;
            *(float4*)(out + rlo + col0 + 4 * np)            = v0;
            *(float4*)(out + rlo + 8 * 128 + col0 + 4 * np)  = v1;
        }
    }
}

extern "C" void kernel_launch(void* const* d_in, const int* in_sizes, int n_in,
                              void* d_out, int out_size) {
    const float* H     = (const float*)d_in[0];
    const float* E     = (const float*)d_in[1];
    const int*   heads = (const int*)d_in[2];
    // d_in[3] = queries (unused)
    const float* W     = (const float*)d_in[4];
    const float* b     = (const float*)d_in[5];
    float* out = (float*)d_out;

    cudaFuncSetAttribute(msg_mma_kernel,
                         cudaFuncAttributeMaxDynamicSharedMemorySize, SMEM_BYTES);

    prep_b16<<<64, 256>>>(W);
    msg_mma_kernel<<<NBLOCKS, 128, SMEM_BYTES>>>(H, E, heads, b, out);
}

// round 10
// speedup vs baseline: 1.0911x; 1.0911x over previous
#include <cuda_runtime.h>
#include <cuda_fp16.h>
#include <cstdint>

#define NBLOCKS 6250
#define ACHUNK_BYTES (128 * 128)            // 128 rows x 64 fp16 cols
#define SMEM_BYTES (2 * ACHUNK_BYTES + 512)

// fp16 B fragments for mma.m16n8k16 (R4/R8-proven layout):
// g_Bf16[(((wn*16 + ks)*32 + lane)*16) + nt*2 + j]
//   = half2(W[wn*64+nt*8+g][ks*16+2t+8j], W[...][...+1])
__device__ uint32_t g_Bf16[16384];          // 64 KB, L1/L2-resident

__global__ void prep_b16(const float* __restrict__ W) {
    int i = blockIdx.x * 256 + threadIdx.x;   // 0..16383
    int wn   = i >> 13;
    int rem  = i & 8191;
    int ks   = rem >> 9;
    int rem2 = rem & 511;
    int lane = rem2 >> 4;
    int idx  = rem2 & 15;
    int nt = idx >> 1, j = idx & 1;
    int g = lane >> 2, t = lane & 3;
    int n = wn * 64 + nt * 8 + g;
    int k = ks * 16 + 2 * t + 8 * j;
    __half2 h = __floats2half2_rn(W[n * 256 + k], W[n * 256 + k + 1]);
    g_Bf16[i] = *(uint32_t*)&h;
}

__device__ __forceinline__ uint32_t smem_u32(const void* p) {
    uint32_t a;
    asm("{ .reg .u64 t; cvta.to.shared.u64 t, %1; cvt.u32.u64 %0, t; }" : "=r"(a) : "l"(p));
    return a;
}
__device__ __forceinline__ uint32_t swz(uint32_t b) {   // 128B rows, 8-row period
    return b ^ (((b >> 7) & 7) << 4);
}
__device__ __forceinline__ uint32_t pack_h2(float x, float y) {
    __half2 h = __floats2half2_rn(x, y);
    return *(uint32_t*)&h;
}
__device__ __forceinline__ void ldsm4(uint32_t& a0, uint32_t& a1, uint32_t& a2,
                                      uint32_t& a3, uint32_t addr) {
    asm volatile("ldmatrix.sync.aligned.m8n8.x4.shared.b16 {%0,%1,%2,%3}, [%4];"
                 : "=r"(a0), "=r"(a1), "=r"(a2), "=r"(a3) : "r"(addr));
}
__device__ __forceinline__ void mma16(float* acc, uint32_t a0, uint32_t a1,
                                      uint32_t a2, uint32_t a3,
                                      uint32_t b0, uint32_t b1) {
    asm volatile(
        "mma.sync.aligned.m16n8k16.row.col.f32.f16.f16.f32 "
        "{%0,%1,%2,%3}, {%4,%5,%6,%7}, {%8,%9}, {%0,%1,%2,%3};\n"
        : "+f"(acc[0]), "+f"(acc[1]), "+f"(acc[2]), "+f"(acc[3])
        : "r"(a0), "r"(a1), "r"(a2), "r"(a3), "r"(b0), "r"(b1));
}

// CTA: 128 edges x 128 outputs. 128 threads = 4 warps (2M x 2N), 64x64 warp tile.
// A fp16-converted at load (LDG->F2FP->STS, SINGLE reg staging set), fragments
// via ldmatrix.x4. B fp16 fragments via LDG, software-prefetched one k-step ahead.
__global__ void __launch_bounds__(128, 2) msg_mma_kernel(
    const float* __restrict__ H,
    const float* __restrict__ E,
    const int*   __restrict__ heads,
    const float* __restrict__ bias,
    float*       __restrict__ out)
{
    extern __shared__ __align__(1024) char smem[];
    float* bias_s = (float*)(smem + 2 * ACHUNK_BYTES);
    const uint32_t sbase = smem_u32(smem);

    const int tid  = threadIdx.x;
    const int warp = tid >> 5;
    const int lane = tid & 31;
    const int warp_m = warp >> 1;
    const int warp_n = warp & 1;
    const int g = lane >> 2;
    const int t = lane & 3;
    const int block_m = blockIdx.x * 128;

    bias_s[tid] = bias[tid];

    // ---- A staging: thread covers rows (tid>>2)+32i, float cols (tid&3)*16.. ----
    const int arow = tid >> 2;
    const int aseg = (tid & 3) * 16;
    int hoff[4];                       // head row indices (ints, not pointers)
    uint32_t sts_a[4], sts_b[4];
    #pragma unroll
    for (int i = 0; i < 4; i++) {
        const int r = arow + 32 * i;
        hoff[i] = heads[block_m + r];
        const uint32_t byt = (uint32_t)(r * 128 + aseg * 2);
        sts_a[i] = swz(byt);
        sts_b[i] = swz(byt + 16);
    }
    const float* Hb = H + aseg;
    const float* Eb = E + (size_t)block_m * 128 + aseg;

    uint4 stg[4][2];                   // SINGLE staging set (32 regs)
    auto ldg_chunk = [&](int c) {
        #pragma unroll
        for (int i = 0; i < 4; i++) {
            const float* s = (c < 2)
                ? (Hb + (size_t)hoff[i] * 128 + (c & 1) * 64)
                : (Eb + (size_t)(arow + 32 * i) * 128 + (c & 1) * 64);
            float4 v0 = *(const float4*)(s + 0);
            float4 v1 = *(const float4*)(s + 4);
            float4 v2 = *(const float4*)(s + 8);
            float4 v3 = *(const float4*)(s + 12);
            stg[i][0] = make_uint4(pack_h2(v0.x, v0.y), pack_h2(v0.z, v0.w),
                                   pack_h2(v1.x, v1.y), pack_h2(v1.z, v1.w));
            stg[i][1] = make_uint4(pack_h2(v2.x, v2.y), pack_h2(v2.z, v2.w),
                                   pack_h2(v3.x, v3.y), pack_h2(v3.z, v3.w));
        }
    };
    auto sts_chunk = [&](int c) {
        const uint32_t off = (uint32_t)((c & 1) * ACHUNK_BYTES);
        #pragma unroll
        for (int i = 0; i < 4; i++) {
            *(uint4*)(smem + off + sts_a[i]) = stg[i][0];
            *(uint4*)(smem + off + sts_b[i]) = stg[i][1];
        }
    };

    // ---- ldmatrix lane bases per mt: UNSWIZZLED; XOR mask applied at use ----
    const int row_sel = (lane & 7) + ((lane >> 3) & 1) * 8;
    const int kb2     = ((lane >> 4) & 1) * 16;
    const uint32_t xmask = (uint32_t)((lane & 7) << 4);
    uint32_t lm[4];
    #pragma unroll
    for (int mt = 0; mt < 4; mt++) {
        const int row0 = warp_m * 64 + mt * 16;
        lm[mt] = sbase + (uint32_t)((row0 + row_sel) * 128 + kb2);
    }

    float acc[2][8][4];
    float acc2[2][8][4];
    #pragma unroll
    for (int mt = 0; mt < 2; mt++)
        #pragma unroll
        for (int nt = 0; nt < 8; nt++)
            #pragma unroll
            for (int i = 0; i < 4; i++) { acc[mt][nt][i] = 0.0f; acc2[mt][nt][i] = 0.0f; }

    const uint4* bbase = (const uint4*)g_Bf16 + (warp_n * 16 * 32 + lane) * 4;

    auto compute = [&](int c) {
        const uint32_t bufoff = (uint32_t)((c & 1) * ACHUNK_BYTES);
        uint4 qa[4], qb[4];
        // prefetch B for ksl=0
        {
            const uint4* bp = bbase + (size_t)(c * 4) * 32 * 4;
            qa[0] = bp[0]; qa[1] = bp[1]; qa[2] = bp[2]; qa[3] = bp[3];
        }
        #pragma unroll
        for (int ksl = 0; ksl < 4; ksl++) {
            const uint4* cur = (ksl & 1) ? qb : qa;
            uint4* nxt = (ksl & 1) ? qa : qb;
            if (ksl < 3) {             // issue next B loads before the mma burst
                const uint4* bp = bbase + (size_t)(c * 4 + ksl + 1) * 32 * 4;
                nxt[0] = bp[0]; nxt[1] = bp[1]; nxt[2] = bp[2]; nxt[3] = bp[3];
            }
            uint32_t bf[8][2] = {
                {cur[0].x, cur[0].y}, {cur[0].z, cur[0].w},
                {cur[1].x, cur[1].y}, {cur[1].z, cur[1].w},
                {cur[2].x, cur[2].y}, {cur[2].z, cur[2].w},
                {cur[3].x, cur[3].y}, {cur[3].z, cur[3].w}};
            #pragma unroll
            for (int mt = 0; mt < 4; mt++) {
                uint32_t a0, a1, a2, a3;
                ldsm4(a0, a1, a2, a3,
                      (lm[mt] + bufoff + (uint32_t)(ksl * 32)) ^ xmask);
                float* arow_p = (mt < 2) ? acc[mt][0] : acc2[mt - 2][0];
                #pragma unroll
                for (int nt = 0; nt < 8; nt++)
                    mma16(arow_p + nt * 4, a0, a1, a2, a3, bf[nt][0], bf[nt][1]);
            }
        }
    };

    // ---- pipeline (single stg set): ldg(c+2) in flight during compute(c) ----
    ldg_chunk(0); sts_chunk(0);
    ldg_chunk(1); sts_chunk(1);
    ldg_chunk(2);
    __syncthreads();
    compute(0);
    __syncthreads();
    sts_chunk(2);
    ldg_chunk(3);
    __syncthreads();
    compute(1);
    __syncthreads();
    sts_chunk(3);
    __syncthreads();
    compute(2);
    compute(3);

    // ---- Epilogue (R8-proven): +bias, float2 stores ----
    #pragma unroll
    for (int mt = 0; mt < 4; mt++) {
        const float* arow_p = (mt < 2) ? acc[mt][0] : acc2[mt - 2][0];
        const int row0 = block_m + warp_m * 64 + mt * 16 + g;
        #pragma unroll
        for (int nt = 0; nt < 8; nt++) {
            const int col = warp_n * 64 + nt * 8 + t * 2;
            float2 bv = *(const float2*)(bias_s + col);
            float2 v0, v1;
            v0.x = arow_p[nt * 4 + 0] + bv.x;
            v0.y = arow_p[nt * 4 + 1] + bv.y;
            v1.x = arow_p[nt * 4 + 2] + bv.x;
            v1.y = arow_p[nt * 4 + 3] + bv.y;
            *(float2*)(out + (size_t)row0 * 128 + col)       = v0;
            *(float2*)(out + (size_t)(row0 + 8) * 128 + col) = v1;
        }
    }
}

extern "C" void kernel_launch(void* const* d_in, const int* in_sizes, int n_in,
                              void* d_out, int out_size) {
    const float* H     = (const float*)d_in[0];
    const float* E     = (const float*)d_in[1];
    const int*   heads = (const int*)d_in[2];
    // d_in[3] = queries (unused)
    const float* W     = (const float*)d_in[4];
    const float* b     = (const float*)d_in[5];
    float* out = (float*)d_out;

    cudaFuncSetAttribute(msg_mma_kernel,
                         cudaFuncAttributeMaxDynamicSharedMemorySize, SMEM_BYTES);

    prep_b16<<<64, 256>>>(W);
    msg_mma_kernel<<<NBLOCKS, 128, SMEM_BYTES>>>(H, E, heads, b, out);
}

// round 11
// speedup vs baseline: 1.1178x; 1.0244x over previous
#include <cuda_runtime.h>
#include <cuda_fp16.h>
#include <cstdint>

#define NBLOCKS 6250
#define ACHUNK_BYTES (128 * 128)            // 128 rows x 64 fp16 cols
#define SMEM_BYTES (2 * ACHUNK_BYTES + 1024)

// fp16 B fragments for mma.m16n8k16 (R4/R8-proven layout):
// g_Bf16[(((wn*16 + ks)*32 + lane)*16) + nt*2 + j]
//   = half2(W[wn*64+nt*8+g][ks*16+2t+8j], W[...][...+1])
__device__ uint32_t g_Bf16[16384];          // 64 KB, L1/L2-resident

__global__ void prep_b16(const float* __restrict__ W) {
    int i = blockIdx.x * 256 + threadIdx.x;   // 0..16383
    int wn   = i >> 13;
    int rem  = i & 8191;
    int ks   = rem >> 9;
    int rem2 = rem & 511;
    int lane = rem2 >> 4;
    int idx  = rem2 & 15;
    int nt = idx >> 1, j = idx & 1;
    int g = lane >> 2, t = lane & 3;
    int n = wn * 64 + nt * 8 + g;
    int k = ks * 16 + 2 * t + 8 * j;
    __half2 h = __floats2half2_rn(W[n * 256 + k], W[n * 256 + k + 1]);
    g_Bf16[i] = *(uint32_t*)&h;
}

__device__ __forceinline__ uint32_t smem_u32(const void* p) {
    uint32_t a;
    asm("{ .reg .u64 t; cvta.to.shared.u64 t, %1; cvt.u32.u64 %0, t; }" : "=r"(a) : "l"(p));
    return a;
}
__device__ __forceinline__ uint32_t pack_h2(float x, float y) {
    __half2 h = __floats2half2_rn(x, y);
    return *(uint32_t*)&h;
}
__device__ __forceinline__ void ldsm4(uint32_t& a0, uint32_t& a1, uint32_t& a2,
                                      uint32_t& a3, uint32_t addr) {
    asm volatile("ldmatrix.sync.aligned.m8n8.x4.shared.b16 {%0,%1,%2,%3}, [%4];"
                 : "=r"(a0), "=r"(a1), "=r"(a2), "=r"(a3) : "r"(addr));
}
__device__ __forceinline__ void mma16(float* acc, uint32_t a0, uint32_t a1,
                                      uint32_t a2, uint32_t a3,
                                      uint32_t b0, uint32_t b1) {
    asm volatile(
        "mma.sync.aligned.m16n8k16.row.col.f32.f16.f16.f32 "
        "{%0,%1,%2,%3}, {%4,%5,%6,%7}, {%8,%9}, {%0,%1,%2,%3};\n"
        : "+f"(acc[0]), "+f"(acc[1]), "+f"(acc[2]), "+f"(acc[3])
        : "r"(a0), "r"(a1), "r"(a2), "r"(a3), "r"(b0), "r"(b1));
}

// CTA: 128 edges x 128 outputs. 128 threads = 4 warps (2M x 2N), 64x64 warp tile.
// A loads: 16 consecutive lanes cover one row's full 256B chunk (2 rows/warp-op,
// dense 128B lines). fp16 conversion at load; STS.64 conflict-free; fragments
// via ldmatrix.x4. B fp16 fragments via LDG, reg double-buffered (R10-proven).
__global__ void __launch_bounds__(128, 2) msg_mma_kernel(
    const float* __restrict__ H,
    const float* __restrict__ E,
    const int*   __restrict__ heads,
    const float* __restrict__ bias,
    float*       __restrict__ out)
{
    extern __shared__ __align__(1024) char smem[];
    float* bias_s  = (float*)(smem + 2 * ACHUNK_BYTES);
    int*   heads_s = (int*)(bias_s + 128);
    const uint32_t sbase = smem_u32(smem);

    const int tid  = threadIdx.x;
    const int warp = tid >> 5;
    const int lane = tid & 31;
    const int warp_m = warp >> 1;
    const int warp_n = warp & 1;
    const int g = lane >> 2;
    const int t = lane & 3;
    const int block_m = blockIdx.x * 128;

    bias_s[tid]  = bias[tid];
    heads_s[tid] = heads[block_m + tid];
    __syncthreads();

    // ---- A-load lane mapping: lane_lo covers 16B of a row; half selects row ----
    const int lane_lo = lane & 15;        // 16B segment within 256B row-chunk
    const int half    = lane >> 4;        // 0/1: which of the 2 rows this op
    const int rbase   = warp * 32 + half; // rows rbase + 2*o, o = 0..15

    uint2 stg[16];                        // 32 regs staging (fp16-packed)
    auto ldg_chunk = [&](int c) {
        const int coff = (c & 1) * 64 + lane_lo * 4;
        #pragma unroll
        for (int o = 0; o < 16; o++) {
            const int row = rbase + o * 2;
            const float* s = (c < 2)
                ? (H + (size_t)heads_s[row] * 128 + coff)
                : (E + (size_t)(block_m + row) * 128 + coff);
            float4 v = *(const float4*)s;
            stg[o] = make_uint2(pack_h2(v.x, v.y), pack_h2(v.z, v.w));
        }
    };
    auto sts_chunk = [&](int c) {
        const uint32_t off = (uint32_t)((c & 1) * ACHUNK_BYTES);
        #pragma unroll
        for (int o = 0; o < 16; o++) {
            const int row = rbase + o * 2;
            uint32_t b = (uint32_t)(row * 128 + lane_lo * 8);
            b ^= (uint32_t)((row & 7) << 4);     // swizzle (8-row period)
            *(uint2*)(smem + off + b) = stg[o];
        }
    };

    // ---- ldmatrix lane bases per mt: UNSWIZZLED; XOR mask applied at use ----
    const int row_sel = (lane & 7) + ((lane >> 3) & 1) * 8;
    const int kb2     = ((lane >> 4) & 1) * 16;
    const uint32_t xmask = (uint32_t)((lane & 7) << 4);
    uint32_t lm[4];
    #pragma unroll
    for (int mt = 0; mt < 4; mt++) {
        const int row0 = warp_m * 64 + mt * 16;
        lm[mt] = sbase + (uint32_t)((row0 + row_sel) * 128 + kb2);
    }

    float acc[2][8][4];
    float acc2[2][8][4];
    #pragma unroll
    for (int mt = 0; mt < 2; mt++)
        #pragma unroll
        for (int nt = 0; nt < 8; nt++)
            #pragma unroll
            for (int i = 0; i < 4; i++) { acc[mt][nt][i] = 0.0f; acc2[mt][nt][i] = 0.0f; }

    const uint4* bbase = (const uint4*)g_Bf16 + (warp_n * 16 * 32 + lane) * 4;

    auto compute = [&](int c) {
        const uint32_t bufoff = (uint32_t)((c & 1) * ACHUNK_BYTES);
        uint4 qa[4], qb[4];
        {
            const uint4* bp = bbase + (size_t)(c * 4) * 32 * 4;
            qa[0] = bp[0]; qa[1] = bp[1]; qa[2] = bp[2]; qa[3] = bp[3];
        }
        #pragma unroll
        for (int ksl = 0; ksl < 4; ksl++) {
            const uint4* cur = (ksl & 1) ? qb : qa;
            uint4* nxt = (ksl & 1) ? qa : qb;
            if (ksl < 3) {
                const uint4* bp = bbase + (size_t)(c * 4 + ksl + 1) * 32 * 4;
                nxt[0] = bp[0]; nxt[1] = bp[1]; nxt[2] = bp[2]; nxt[3] = bp[3];
            }
            uint32_t bf[8][2] = {
                {cur[0].x, cur[0].y}, {cur[0].z, cur[0].w},
                {cur[1].x, cur[1].y}, {cur[1].z, cur[1].w},
                {cur[2].x, cur[2].y}, {cur[2].z, cur[2].w},
                {cur[3].x, cur[3].y}, {cur[3].z, cur[3].w}};
            #pragma unroll
            for (int mt = 0; mt < 4; mt++) {
                uint32_t a0, a1, a2, a3;
                ldsm4(a0, a1, a2, a3,
                      (lm[mt] + bufoff + (uint32_t)(ksl * 32)) ^ xmask);
                float* arow_p = (mt < 2) ? acc[mt][0] : acc2[mt - 2][0];
                #pragma unroll
                for (int nt = 0; nt < 8; nt++)
                    mma16(arow_p + nt * 4, a0, a1, a2, a3, bf[nt][0], bf[nt][1]);
            }
        }
    };

    // ---- pipeline (single stg set): ldg(c+2) in flight during compute(c) ----
    ldg_chunk(0); sts_chunk(0);
    ldg_chunk(1); sts_chunk(1);
    ldg_chunk(2);
    __syncthreads();
    compute(0);
    __syncthreads();
    sts_chunk(2);
    ldg_chunk(3);
    __syncthreads();
    compute(1);
    __syncthreads();
    sts_chunk(3);
    __syncthreads();
    compute(2);
    compute(3);

    // ---- Epilogue (R8-proven): +bias, float2 stores ----
    #pragma unroll
    for (int mt = 0; mt < 4; mt++) {
        const float* arow_p = (mt < 2) ? acc[mt][0] : acc2[mt - 2][0];
        const int row0 = block_m + warp_m * 64 + mt * 16 + g;
        #pragma unroll
        for (int nt = 0; nt < 8; nt++) {
            const int col = warp_n * 64 + nt * 8 + t * 2;
            float2 bv = *(const float2*)(bias_s + col);
            float2 v0, v1;
            v0.x = arow_p[nt * 4 + 0] + bv.x;
            v0.y = arow_p[nt * 4 + 1] + bv.y;
            v1.x = arow_p[nt * 4 + 2] + bv.x;
            v1.y = arow_p[nt * 4 + 3] + bv.y;
            *(float2*)(out + (size_t)row0 * 128 + col)       = v0;
            *(float2*)(out + (size_t)(row0 + 8) * 128 + col) = v1;
        }
    }
}

extern "C" void kernel_launch(void* const* d_in, const int* in_sizes, int n_in,
                              void* d_out, int out_size) {
    const float* H     = (const float*)d_in[0];
    const float* E     = (const float*)d_in[1];
    const int*   heads = (const int*)d_in[2];
    // d_in[3] = queries (unused)
    const float* W     = (const float*)d_in[4];
    const float* b     = (const float*)d_in[5];
    float* out = (float*)d_out;

    cudaFuncSetAttribute(msg_mma_kernel,
                         cudaFuncAttributeMaxDynamicSharedMemorySize, SMEM_BYTES);

    prep_b16<<<64, 256>>>(W);
    msg_mma_kernel<<<NBLOCKS, 128, SMEM_BYTES>>>(H, E, heads, b, out);
}

// round 12
// speedup vs baseline: 1.1808x; 1.0564x over previous
#include <cuda_runtime.h>
#include <cuda_fp16.h>
#include <cstdint>

#define NBLOCKS 6250
#define ACHUNK_BYTES (128 * 128)            // 128 rows x 64 fp16 cols
#define SMEM_BYTES (2 * ACHUNK_BYTES + 1024)

// fp16 B fragments for mma.m16n8k16, 4 N-groups of 32 cols:
// g_Bf16[(((wn4*16 + ks)*32 + lane)*8) + nt*2 + j]
//   = half2(W[wn4*32+nt*8+g][ks*16+2t+8j], W[...][...+1])
__device__ uint32_t g_Bf16[16384];          // 64 KB, L1/L2-resident

__global__ void prep_b16(const float* __restrict__ W) {
    int i = blockIdx.x * 256 + threadIdx.x;   // 0..16383
    int wn4  = i >> 12;          // 0..3
    int ks   = (i >> 8) & 15;    // 0..15
    int lane = (i >> 3) & 31;
    int idx  = i & 7;
    int nt = idx >> 1, j = idx & 1;
    int g = lane >> 2, t = lane & 3;
    int n = wn4 * 32 + nt * 8 + g;
    int k = ks * 16 + 2 * t + 8 * j;
    __half2 h = __floats2half2_rn(W[n * 256 + k], W[n * 256 + k + 1]);
    g_Bf16[i] = *(uint32_t*)&h;
}

__device__ __forceinline__ uint32_t smem_u32(const void* p) {
    uint32_t a;
    asm("{ .reg .u64 t; cvta.to.shared.u64 t, %1; cvt.u32.u64 %0, t; }" : "=r"(a) : "l"(p));
    return a;
}
__device__ __forceinline__ uint32_t pack_h2(float x, float y) {
    __half2 h = __floats2half2_rn(x, y);
    return *(uint32_t*)&h;
}
__device__ __forceinline__ void ldsm4(uint32_t& a0, uint32_t& a1, uint32_t& a2,
                                      uint32_t& a3, uint32_t addr) {
    asm volatile("ldmatrix.sync.aligned.m8n8.x4.shared.b16 {%0,%1,%2,%3}, [%4];"
                 : "=r"(a0), "=r"(a1), "=r"(a2), "=r"(a3) : "r"(addr));
}
__device__ __forceinline__ void mma16(float* acc, uint32_t a0, uint32_t a1,
                                      uint32_t a2, uint32_t a3,
                                      uint32_t b0, uint32_t b1) {
    asm volatile(
        "mma.sync.aligned.m16n8k16.row.col.f32.f16.f16.f32 "
        "{%0,%1,%2,%3}, {%4,%5,%6,%7}, {%8,%9}, {%0,%1,%2,%3};\n"
        : "+f"(acc[0]), "+f"(acc[1]), "+f"(acc[2]), "+f"(acc[3])
        : "r"(a0), "r"(a1), "r"(a2), "r"(a3), "r"(b0), "r"(b1));
}

// CTA: 128 edges x 128 outputs. 256 threads = 8 warps (2M x 4N), warp tile 64x32.
// acc=64 regs -> 2 CTAs/SM = 16 warps (4/SMSP) for latency hiding.
// A loads dense-line (R11-proven); fragments via ldmatrix.x4; B via LDG dbuf.
__global__ void __launch_bounds__(256, 2) msg_mma_kernel(
    const float* __restrict__ H,
    const float* __restrict__ E,
    const int*   __restrict__ heads,
    const float* __restrict__ bias,
    float*       __restrict__ out)
{
    extern __shared__ __align__(1024) char smem[];
    float* bias_s  = (float*)(smem + 2 * ACHUNK_BYTES);
    int*   heads_s = (int*)(bias_s + 128);
    const uint32_t sbase = smem_u32(smem);

    const int tid  = threadIdx.x;
    const int warp = tid >> 5;
    const int lane = tid & 31;
    const int warp_m = warp >> 2;        // 0..1 -> rows warp_m*64
    const int warp_n = warp & 3;         // 0..3 -> cols warp_n*32
    const int g = lane >> 2;
    const int t = lane & 3;
    const int block_m = blockIdx.x * 128;

    if (tid < 128) {
        bias_s[tid]  = bias[tid];
        heads_s[tid] = heads[block_m + tid];
    }
    __syncthreads();

    // ---- A-load lane mapping: 16 lanes cover one row's 64-float chunk ----
    const int lane_lo = lane & 15;
    const int half    = lane >> 4;
    const int rbase   = warp * 16 + half;   // rows rbase + 2*o, o = 0..7

    uint2 stg[8];                           // 16 regs staging
    auto ldg_chunk = [&](int c) {
        const int coff = (c & 1) * 64 + lane_lo * 4;
        #pragma unroll
        for (int o = 0; o < 8; o++) {
            const int row = rbase + o * 2;
            const float* s = (c < 2)
                ? (H + (size_t)heads_s[row] * 128 + coff)
                : (E + (size_t)(block_m + row) * 128 + coff);
            float4 v = *(const float4*)s;
            stg[o] = make_uint2(pack_h2(v.x, v.y), pack_h2(v.z, v.w));
        }
    };
    auto sts_chunk = [&](int c) {
        const uint32_t off = (uint32_t)((c & 1) * ACHUNK_BYTES);
        #pragma unroll
        for (int o = 0; o < 8; o++) {
            const int row = rbase + o * 2;
            uint32_t b = (uint32_t)(row * 128 + lane_lo * 8);
            b ^= (uint32_t)((row & 7) << 4);
            *(uint2*)(smem + off + b) = stg[o];
        }
    };

    // ---- ldmatrix lane bases per mt: UNSWIZZLED; XOR mask applied at use ----
    const int row_sel = (lane & 7) + ((lane >> 3) & 1) * 8;
    const int kb2     = ((lane >> 4) & 1) * 16;
    const uint32_t xmask = (uint32_t)((lane & 7) << 4);
    uint32_t lm[4];
    #pragma unroll
    for (int mt = 0; mt < 4; mt++) {
        const int row0 = warp_m * 64 + mt * 16;
        lm[mt] = sbase + (uint32_t)((row0 + row_sel) * 128 + kb2);
    }

    float acc[4][4][4];                     // 64 regs
    #pragma unroll
    for (int mt = 0; mt < 4; mt++)
        #pragma unroll
        for (int nt = 0; nt < 4; nt++)
            #pragma unroll
            for (int i = 0; i < 4; i++) acc[mt][nt][i] = 0.0f;

    const uint4* bbase = (const uint4*)g_Bf16 + (warp_n * 16 * 32 + lane) * 2;

    auto compute = [&](int c) {
        const uint32_t bufoff = (uint32_t)((c & 1) * ACHUNK_BYTES);
        uint4 qa[2], qb[2];
        {
            const uint4* bp = bbase + (size_t)(c * 4) * 32 * 2;
            qa[0] = bp[0]; qa[1] = bp[1];
        }
        #pragma unroll
        for (int ksl = 0; ksl < 4; ksl++) {
            const uint4* cur = (ksl & 1) ? qb : qa;
            uint4* nxt = (ksl & 1) ? qa : qb;
            if (ksl < 3) {
                const uint4* bp = bbase + (size_t)(c * 4 + ksl + 1) * 32 * 2;
                nxt[0] = bp[0]; nxt[1] = bp[1];
            }
            uint32_t bf[4][2] = {
                {cur[0].x, cur[0].y}, {cur[0].z, cur[0].w},
                {cur[1].x, cur[1].y}, {cur[1].z, cur[1].w}};
            #pragma unroll
            for (int mt = 0; mt < 4; mt++) {
                uint32_t a0, a1, a2, a3;
                ldsm4(a0, a1, a2, a3,
                      (lm[mt] + bufoff + (uint32_t)(ksl * 32)) ^ xmask);
                #pragma unroll
                for (int nt = 0; nt < 4; nt++)
                    mma16(acc[mt][nt], a0, a1, a2, a3, bf[nt][0], bf[nt][1]);
            }
        }
    };

    // ---- pipeline (single stg set): ldg(c+2) in flight during compute(c) ----
    ldg_chunk(0); sts_chunk(0);
    ldg_chunk(1); sts_chunk(1);
    ldg_chunk(2);
    __syncthreads();
    compute(0);
    __syncthreads();
    sts_chunk(2);
    ldg_chunk(3);
    __syncthreads();
    compute(1);
    __syncthreads();
    sts_chunk(3);
    __syncthreads();
    compute(2);
    compute(3);

    // ---- Epilogue: +bias, float2 stores ----
    #pragma unroll
    for (int mt = 0; mt < 4; mt++) {
        const int row0 = block_m + warp_m * 64 + mt * 16 + g;
        #pragma unroll
        for (int nt = 0; nt < 4; nt++) {
            const int col = warp_n * 32 + nt * 8 + t * 2;
            float2 bv = *(const float2*)(bias_s + col);
            float2 v0, v1;
            v0.x = acc[mt][nt][0] + bv.x;
            v0.y = acc[mt][nt][1] + bv.y;
            v1.x = acc[mt][nt][2] + bv.x;
            v1.y = acc[mt][nt][3] + bv.y;
            *(float2*)(out + (size_t)row0 * 128 + col)       = v0;
            *(float2*)(out + (size_t)(row0 + 8) * 128 + col) = v1;
        }
    }
}

extern "C" void kernel_launch(void* const* d_in, const int* in_sizes, int n_in,
                              void* d_out, int out_size) {
    const float* H     = (const float*)d_in[0];
    const float* E     = (const float*)d_in[1];
    const int*   heads = (const int*)d_in[2];
    // d_in[3] = queries (unused)
    const float* W     = (const float*)d_in[4];
    const float* b     = (const float*)d_in[5];
    float* out = (float*)d_out;

    cudaFuncSetAttribute(msg_mma_kernel,
                         cudaFuncAttributeMaxDynamicSharedMemorySize, SMEM_BYTES);

    prep_b16<<<64, 256>>>(W);
    msg_mma_kernel<<<NBLOCKS, 256, SMEM_BYTES>>>(H, E, heads, b, out);
}

// round 13
// speedup vs baseline: 1.5055x; 1.2749x over previous
#include <cuda_runtime.h>
#include <cuda_fp16.h>
#include <cstdint>

#define NBLOCKS 6250
#define ACHUNK_BYTES (128 * 128)            // 128 rows x 64 fp16 cols
#define SMEM_BYTES (4 * ACHUNK_BYTES + 1024)

// fp16 B fragments for mma.m16n8k16, 4 N-groups of 32 cols (R12-proven):
// g_Bf16[(((wn4*16 + ks)*32 + lane)*8) + nt*2 + j]
//   = half2(W[wn4*32+nt*8+g][ks*16+2t+8j], W[...][...+1])
__device__ uint32_t g_Bf16[16384];          // 64 KB, L1/L2-resident

__global__ void prep_b16(const float* __restrict__ W) {
    int i = blockIdx.x * 256 + threadIdx.x;   // 0..16383
    int wn4  = i >> 12;          // 0..3
    int ks   = (i >> 8) & 15;    // 0..15
    int lane = (i >> 3) & 31;
    int idx  = i & 7;
    int nt = idx >> 1, j = idx & 1;
    int g = lane >> 2, t = lane & 3;
    int n = wn4 * 32 + nt * 8 + g;
    int k = ks * 16 + 2 * t + 8 * j;
    __half2 h = __floats2half2_rn(W[n * 256 + k], W[n * 256 + k + 1]);
    g_Bf16[i] = *(uint32_t*)&h;
}

__device__ __forceinline__ uint32_t smem_u32(const void* p) {
    uint32_t a;
    asm("{ .reg .u64 t; cvta.to.shared.u64 t, %1; cvt.u32.u64 %0, t; }" : "=r"(a) : "l"(p));
    return a;
}
__device__ __forceinline__ uint32_t pack_h2(float x, float y) {
    __half2 h = __floats2half2_rn(x, y);
    return *(uint32_t*)&h;
}
__device__ __forceinline__ void ldsm4(uint32_t& a0, uint32_t& a1, uint32_t& a2,
                                      uint32_t& a3, uint32_t addr) {
    asm volatile("ldmatrix.sync.aligned.m8n8.x4.shared.b16 {%0,%1,%2,%3}, [%4];"
                 : "=r"(a0), "=r"(a1), "=r"(a2), "=r"(a3) : "r"(addr));
}
__device__ __forceinline__ void mma16(float* acc, uint32_t a0, uint32_t a1,
                                      uint32_t a2, uint32_t a3,
                                      uint32_t b0, uint32_t b1) {
    asm volatile(
        "mma.sync.aligned.m16n8k16.row.col.f32.f16.f16.f32 "
        "{%0,%1,%2,%3}, {%4,%5,%6,%7}, {%8,%9}, {%0,%1,%2,%3};\n"
        : "+f"(acc[0]), "+f"(acc[1]), "+f"(acc[2]), "+f"(acc[3])
        : "r"(a0), "r"(a1), "r"(a2), "r"(a3), "r"(b0), "r"(b1));
}

// CTA: 128 edges x 128 outputs. 256 threads = 8 warps (2M x 4N), warp tile 64x32.
// ALL of K staged up front into 4 smem buffers -> ONE barrier, then an
// unbroken 16-kstep mma stream. E via __ldcs, out via __stcs (L2 streaming).
__global__ void __launch_bounds__(256, 2) msg_mma_kernel(
    const float* __restrict__ H,
    const float* __restrict__ E,
    const int*   __restrict__ heads,
    const float* __restrict__ bias,
    float*       __restrict__ out)
{
    extern __shared__ __align__(1024) char smem[];
    float* bias_s  = (float*)(smem + 4 * ACHUNK_BYTES);
    int*   heads_s = (int*)(bias_s + 128);
    const uint32_t sbase = smem_u32(smem);

    const int tid  = threadIdx.x;
    const int warp = tid >> 5;
    const int lane = tid & 31;
    const int warp_m = warp >> 2;        // 0..1 -> rows warp_m*64
    const int warp_n = warp & 3;         // 0..3 -> cols warp_n*32
    const int g = lane >> 2;
    const int t = lane & 3;
    const int block_m = blockIdx.x * 128;

    if (tid < 128) {
        bias_s[tid]  = bias[tid];
        heads_s[tid] = heads[block_m + tid];
    }
    __syncthreads();

    // ---- A-load lane mapping: 16 lanes cover one row's 64-float chunk ----
    const int lane_lo = lane & 15;
    const int half    = lane >> 4;
    const int rbase   = warp * 16 + half;   // rows rbase + 2*o, o = 0..7

    uint2 stg[8];
    auto ldg_chunk = [&](int c) {
        const int coff = (c & 1) * 64 + lane_lo * 4;
        #pragma unroll
        for (int o = 0; o < 8; o++) {
            const int row = rbase + o * 2;
            float4 v;
            if (c < 2) {
                v = *(const float4*)(H + (size_t)heads_s[row] * 128 + coff);
            } else {
                v = __ldcs((const float4*)(E + (size_t)(block_m + row) * 128 + coff));
            }
            stg[o] = make_uint2(pack_h2(v.x, v.y), pack_h2(v.z, v.w));
        }
    };
    auto sts_chunk = [&](int c) {
        const uint32_t off = (uint32_t)(c * ACHUNK_BYTES);
        #pragma unroll
        for (int o = 0; o < 8; o++) {
            const int row = rbase + o * 2;
            uint32_t b = (uint32_t)(row * 128 + lane_lo * 8);
            b ^= (uint32_t)((row & 7) << 4);
            *(uint2*)(smem + off + b) = stg[o];
        }
    };

    // ---- ldmatrix lane bases per mt: UNSWIZZLED; XOR mask applied at use ----
    const int row_sel = (lane & 7) + ((lane >> 3) & 1) * 8;
    const int kb2     = ((lane >> 4) & 1) * 16;
    const uint32_t xmask = (uint32_t)((lane & 7) << 4);
    uint32_t lm[4];
    #pragma unroll
    for (int mt = 0; mt < 4; mt++) {
        const int row0 = warp_m * 64 + mt * 16;
        lm[mt] = sbase + (uint32_t)((row0 + row_sel) * 128 + kb2);
    }

    float acc[4][4][4];                     // 64 regs
    #pragma unroll
    for (int mt = 0; mt < 4; mt++)
        #pragma unroll
        for (int nt = 0; nt < 4; nt++)
            #pragma unroll
            for (int i = 0; i < 4; i++) acc[mt][nt][i] = 0.0f;

    // ---- stage ALL of K, then one barrier ----
    ldg_chunk(0); sts_chunk(0);
    ldg_chunk(1); sts_chunk(1);
    ldg_chunk(2); sts_chunk(2);
    ldg_chunk(3); sts_chunk(3);
    __syncthreads();

    // ---- unbroken compute: 16 k-steps, B reg double-buffered ----
    const uint4* bbase = (const uint4*)g_Bf16 + (warp_n * 16 * 32 + lane) * 2;
    uint4 qa[2], qb[2];
    {
        const uint4* bp = bbase;
        qa[0] = bp[0]; qa[1] = bp[1];
    }
    #pragma unroll
    for (int ks = 0; ks < 16; ks++) {
        const uint4* cur = (ks & 1) ? qb : qa;
        uint4* nxt = (ks & 1) ? qa : qb;
        if (ks < 15) {
            const uint4* bp = bbase + (size_t)(ks + 1) * 32 * 2;
            nxt[0] = bp[0]; nxt[1] = bp[1];
        }
        uint32_t bf[4][2] = {
            {cur[0].x, cur[0].y}, {cur[0].z, cur[0].w},
            {cur[1].x, cur[1].y}, {cur[1].z, cur[1].w}};
        const uint32_t aoff = (uint32_t)((ks >> 2) * ACHUNK_BYTES + (ks & 3) * 32);
        #pragma unroll
        for (int mt = 0; mt < 4; mt++) {
            uint32_t a0, a1, a2, a3;
            ldsm4(a0, a1, a2, a3, (lm[mt] + aoff) ^ xmask);
            #pragma unroll
            for (int nt = 0; nt < 4; nt++)
                mma16(acc[mt][nt], a0, a1, a2, a3, bf[nt][0], bf[nt][1]);
        }
    }

    // ---- Epilogue: +bias, streaming float2 stores ----
    #pragma unroll
    for (int mt = 0; mt < 4; mt++) {
        const int row0 = block_m + warp_m * 64 + mt * 16 + g;
        #pragma unroll
        for (int nt = 0; nt < 4; nt++) {
            const int col = warp_n * 32 + nt * 8 + t * 2;
            float2 bv = *(const float2*)(bias_s + col);
            float2 v0, v1;
            v0.x = acc[mt][nt][0] + bv.x;
            v0.y = acc[mt][nt][1] + bv.y;
            v1.x = acc[mt][nt][2] + bv.x;
            v1.y = acc[mt][nt][3] + bv.y;
            __stcs((float2*)(out + (size_t)row0 * 128 + col), v0);
            __stcs((float2*)(out + (size_t)(row0 + 8) * 128 + col), v1);
        }
    }
}

extern "C" void kernel_launch(void* const* d_in, const int* in_sizes, int n_in,
                              void* d_out, int out_size) {
    const float* H     = (const float*)d_in[0];
    const float* E     = (const float*)d_in[1];
    const int*   heads = (const int*)d_in[2];
    // d_in[3] = queries (unused)
    const float* W     = (const float*)d_in[4];
    const float* b     = (const float*)d_in[5];
    float* out = (float*)d_out;

    cudaFuncSetAttribute(msg_mma_kernel,
                         cudaFuncAttributeMaxDynamicSharedMemorySize, SMEM_BYTES);

    prep_b16<<<64, 256>>>(W);
    msg_mma_kernel<<<NBLOCKS, 256, SMEM_BYTES>>>(H, E, heads, b, out);
}